// round 1
// baseline (speedup 1.0000x reference)
#include <cuda_runtime.h>
#include <cuda_bf16.h>
#include <math.h>

// Problem constants (fixed by the reference)
#define B 4
#define T 1024
#define D 512
#define U 32
#define WIDTH 64
#define EPS 1e-7f

// Scratch for q (with bh folded in) and k projections: [B, T, U]
__device__ float g_q[B * T * U];
__device__ float g_k[B * T * U];

// ---------------------------------------------------------------------------
// Kernel A: compute q = x@Wt + bh and k = x@Wx for one (b,t) row per block.
// Block = 256 threads. 64 outputs (32 q + 32 k), each computed by a group of
// 4 threads striding over D=512, combined via shfl.
// ---------------------------------------------------------------------------
__global__ void qk_kernel(const float* __restrict__ x,
                          const float* __restrict__ Wt,
                          const float* __restrict__ Wx,
                          const float* __restrict__ bh,
                          float* __restrict__ gq,
                          float* __restrict__ gk) {
    const int row = blockIdx.x;            // b*T + t
    const int tid = threadIdx.x;           // 0..255

    __shared__ float xs[D];
    const float* xr = x + (size_t)row * D;
    xs[tid]       = xr[tid];
    xs[tid + 256] = xr[tid + 256];
    __syncthreads();

    const int o    = tid >> 2;             // output index 0..63
    const int part = tid & 3;              // 0..3
    const int u    = o & (U - 1);          // 0..31
    const float* W = (o < U) ? Wt : Wx;

    float acc = 0.0f;
    #pragma unroll 8
    for (int d = part; d < D; d += 4) {
        acc += xs[d] * W[d * U + u];
    }
    // reduce within the group of 4 contiguous lanes
    acc += __shfl_down_sync(0xffffffffu, acc, 2);
    acc += __shfl_down_sync(0xffffffffu, acc, 1);

    if (part == 0) {
        if (o < U) gq[(size_t)row * U + u] = acc + bh[u];
        else       gk[(size_t)row * U + u] = acc;
    }
}

// ---------------------------------------------------------------------------
// Kernel B: for one (b,t) per block, compute banded attention weights over
// j in [t-32, t+31] and the weighted sum over x.
// ---------------------------------------------------------------------------
__global__ void attn_kernel(const float* __restrict__ x,
                            const float* __restrict__ gq,
                            const float* __restrict__ gk,
                            const float* __restrict__ Wa,
                            const float* __restrict__ ba,
                            float* __restrict__ out) {
    const int row = blockIdx.x;            // b*T + t
    const int b   = row >> 10;             // T = 1024
    const int t   = row & (T - 1);
    const int tid = threadIdx.x;           // 0..255

    __shared__ float qs[U];
    __shared__ float was[U];
    __shared__ float ks[WIDTH * U];
    __shared__ float e[WIDTH];
    __shared__ float s_sum;

    if (tid < U) {
        qs[tid]  = gq[(size_t)row * U + tid];
        was[tid] = Wa[tid];
    }

    int jlo = t - WIDTH / 2;       if (jlo < 0) jlo = 0;
    int jhi = t + (WIDTH - 1) / 2; if (jhi > T - 1) jhi = T - 1;
    const int n = jhi - jlo + 1;   // <= 64

    // load k window into smem (contiguous)
    const float* kb = gk + ((size_t)b * T + jlo) * U;
    for (int i = tid; i < n * U; i += 256) ks[i] = kb[i];
    __syncthreads();

    // scores
    if (tid < WIDTH) {
        float ev = 0.0f;
        if (tid < n) {
            float s = 0.0f;
            #pragma unroll
            for (int u = 0; u < U; u++) {
                s += tanhf(qs[u] + ks[tid * U + u]) * was[u];
            }
            ev = expf(s + ba[0]);
        }
        e[tid] = ev;
    }
    __syncthreads();

    // reduce sum over 64 entries with warp 0
    if (tid < 32) {
        float s = e[tid] + e[tid + 32];
        #pragma unroll
        for (int off = 16; off > 0; off >>= 1)
            s += __shfl_down_sync(0xffffffffu, s, off);
        if (tid == 0) s_sum = s;
    }
    __syncthreads();

    const float inv = 1.0f / (s_sum + EPS);

    // v = (e . x_window) * inv ; coalesced over d
    const float* xb = x + ((size_t)b * T + jlo) * D;
    float* outr = out + (size_t)row * D;
    for (int d = tid; d < D; d += 256) {
        float acc = 0.0f;
        #pragma unroll 4
        for (int jj = 0; jj < n; jj++) {
            acc += e[jj] * xb[(size_t)jj * D + d];
        }
        outr[d] = acc * inv;
    }
}

extern "C" void kernel_launch(void* const* d_in, const int* in_sizes, int n_in,
                              void* d_out, int out_size) {
    const float* x  = (const float*)d_in[0];
    const float* Wt = (const float*)d_in[1];
    const float* Wx = (const float*)d_in[2];
    const float* bh = (const float*)d_in[3];
    const float* Wa = (const float*)d_in[4];
    const float* ba = (const float*)d_in[5];
    float* out = (float*)d_out;

    float* gq;
    float* gk;
    cudaGetSymbolAddress((void**)&gq, g_q);
    cudaGetSymbolAddress((void**)&gk, g_k);

    qk_kernel<<<B * T, 256>>>(x, Wt, Wx, bh, gq, gk);
    attn_kernel<<<B * T, 256>>>(x, gq, gk, Wa, ba, out);
}

// round 2
// speedup vs baseline: 1.9321x; 1.9321x over previous
#include <cuda_runtime.h>
#include <cuda_bf16.h>
#include <math.h>

// Problem constants (fixed by the reference)
#define B 4
#define T 1024
#define D 512
#define U 32
#define WIDTH 64
#define EPS 1e-7f
#define TT 32                 // t-tile per block in attn kernel
#define JW 95                 // window rows per tile: TT + WIDTH - 1

// Scratch: q (bh folded) and k projections, [B,T,U]
__device__ __align__(16) float g_q[B * T * U];
__device__ __align__(16) float g_k[B * T * U];

// packed fp32x2 FMA: acc = a*b + acc (lane-wise on the 2 floats)
__device__ __forceinline__ void fma2(unsigned long long& acc,
                                     unsigned long long a,
                                     unsigned long long b) {
    asm("fma.rn.f32x2 %0, %1, %2, %0;" : "+l"(acc) : "l"(a), "l"(b));
}

// ---------------------------------------------------------------------------
// Kernel A: q = x@Wt + bh ; k = x@Wx.  8 rows per block, 128 threads.
// Each warp: 2 rows; lane = (half, g): half picks row, g picks a 4-u group
// (g<8 -> Wt cols 4g.., g>=8 -> Wx cols 4(g-8)..). x staged duplicated {x,x}.
// ---------------------------------------------------------------------------
__global__ __launch_bounds__(128) void qk_kernel(
    const float4* __restrict__ x4,
    const float*  __restrict__ Wt,
    const float*  __restrict__ Wx,
    const float4* __restrict__ bh4,
    float4* __restrict__ gq4,
    float4* __restrict__ gk4) {
    __shared__ float2 xs2[8][D];   // 32 KB, duplicated pairs

    const int tid  = threadIdx.x;
    const int row0 = blockIdx.x * 8;

    // stage 8 rows, duplicated
    for (int i = tid; i < 8 * 128; i += 128) {
        const int r = i >> 7, c = i & 127;
        float4 v = x4[(size_t)(row0 + r) * 128 + c];
        xs2[r][c * 4 + 0] = make_float2(v.x, v.x);
        xs2[r][c * 4 + 1] = make_float2(v.y, v.y);
        xs2[r][c * 4 + 2] = make_float2(v.z, v.z);
        xs2[r][c * 4 + 3] = make_float2(v.w, v.w);
    }
    __syncthreads();

    const int w    = tid >> 5;
    const int lane = tid & 31;
    const int half = lane >> 4;
    const int g    = lane & 15;
    const int r    = w * 2 + half;     // local row 0..7

    // W viewed as [D][8] float4 (= [D][32] floats)
    const ulonglong2* Wb = (g < 8)
        ? reinterpret_cast<const ulonglong2*>(Wt) + g
        : reinterpret_cast<const ulonglong2*>(Wx) + (g - 8);

    unsigned long long a0 = 0ULL, a1 = 0ULL;
    const float2* xr = xs2[r];

    #pragma unroll 8
    for (int d = 0; d < D; d++) {
        float2 xv = xr[d];
        unsigned long long xp = *reinterpret_cast<unsigned long long*>(&xv);
        ulonglong2 wv = Wb[d * 8];
        fma2(a0, xp, wv.x);   // u0,u1
        fma2(a1, xp, wv.y);   // u2,u3
    }

    const float2 f0 = *reinterpret_cast<float2*>(&a0);
    const float2 f1 = *reinterpret_cast<float2*>(&a1);
    const int row = row0 + r;

    if (g < 8) {
        float4 bb = bh4[g];
        float4 o = make_float4(f0.x + bb.x, f0.y + bb.y, f1.x + bb.z, f1.y + bb.w);
        gq4[(size_t)row * 8 + g] = o;
    } else {
        float4 o = make_float4(f0.x, f0.y, f1.x, f1.y);
        gk4[(size_t)row * 8 + (g - 8)] = o;
    }
}

// ---------------------------------------------------------------------------
// Kernel B: banded attention, TT=32 t's per block, 256 threads.
// Phase 1: scores e[jj][tt] (95x32) via fast tanh.
// Phase 2: register-tiled scatter over the 95-row x window with FFMA2.
// ---------------------------------------------------------------------------
__global__ __launch_bounds__(256) void attn_kernel(
    const float4* __restrict__ x4,
    const float*  __restrict__ gq,
    const float*  __restrict__ gk,
    const float*  __restrict__ Wa,
    const float*  __restrict__ ba,
    float4* __restrict__ out4) {
    __shared__ float  es[JW * 33];       // raw scores, padded stride 33
    __shared__ float2 e2s[JW * 32];      // normalized, duplicated {e,e}
    __shared__ float  was[U];
    __shared__ float  inv_s[TT];
    __shared__ float  ba_s;

    // phase-1 q/k tiles overlay the e2s region (dead until after phase 1)
    float* qs = reinterpret_cast<float*>(e2s);          // 32*33 = 1056 floats
    float* ks = qs + TT * 33;                            // 95*33 = 3135 floats

    const int tid   = threadIdx.x;
    const int blk   = blockIdx.x;
    const int b     = blk >> 5;          // T/TT = 32 tiles per batch
    const int t0    = (blk & 31) * TT;
    const int jbase = t0 - WIDTH / 2;    // global j of jj=0 (may be <0)

    if (tid < U)  was[tid] = Wa[tid];
    if (tid == 0) ba_s = ba[0];

    // load q rows (always in range)
    for (int i = tid; i < TT * U; i += 256) {
        const int tt = i >> 5, u = i & 31;
        qs[tt * 33 + u] = gq[((size_t)(b * T + t0 + tt)) * U + u];
    }
    // load k window rows, zero-fill out of range
    for (int i = tid; i < JW * U; i += 256) {
        const int jj = i >> 5, u = i & 31;
        const int j = jbase + jj;
        ks[jj * 33 + u] = (j >= 0 && j < T)
            ? gk[((size_t)(b * T + j)) * U + u] : 0.0f;
    }
    __syncthreads();

    // phase 1: scores. valid iff j in range and tt <= jj <= tt+63
    for (int idx = tid; idx < JW * TT; idx += 256) {
        const int jj = idx >> 5, tt = idx & 31;
        const int j = jbase + jj;
        float ev = 0.0f;
        if (j >= 0 && j < T && jj >= tt && jj <= tt + (WIDTH - 1)) {
            float s = 0.0f;
            #pragma unroll
            for (int u = 0; u < U; u++) {
                const float arg = qs[tt * 33 + u] + ks[jj * 33 + u];
                const float ex = __expf(2.0f * arg);
                const float th = __fdividef(ex - 1.0f, ex + 1.0f);
                s = fmaf(th, was[u], s);
            }
            ev = __expf(s + ba_s);
        }
        es[jj * 33 + tt] = ev;
    }
    __syncthreads();

    // row sums + inverse
    if (tid < TT) {
        float s = 0.0f;
        #pragma unroll 5
        for (int jj = 0; jj < JW; jj++) s += es[jj * 33 + tid];
        inv_s[tid] = __fdividef(1.0f, s + EPS);
    }
    __syncthreads();

    // build normalized duplicated weights (overwrites qs/ks region)
    for (int idx = tid; idx < JW * TT; idx += 256) {
        const int jj = idx >> 5, tt = idx & 31;
        const float v = es[jj * 33 + tt] * inv_s[tt];
        e2s[jj * 32 + tt] = make_float2(v, v);
    }
    __syncthreads();

    // phase 2: v[tt][d] = sum_jj e[tt][jj] * x[jbase+jj][d]
    // thread: dg = float4 group of d (0..127), h = which 16-t half
    const int dg  = tid & 127;
    const int h   = tid >> 7;
    const int ttb = h * 16;

    unsigned long long acc[16][2];
    #pragma unroll
    for (int k = 0; k < 16; k++) { acc[k][0] = 0ULL; acc[k][1] = 0ULL; }

    const int jlo = ttb;
    const int jhi = min(ttb + 15 + (WIDTH - 1), JW - 1);
    const size_t xbase = (size_t)b * T;

    int jc0 = jbase + jlo;
    jc0 = min(max(jc0, 0), T - 1);
    float4 xv = x4[(xbase + jc0) * 128 + dg];

    for (int jj = jlo; jj <= jhi; jj++) {
        float4 xnext = xv;
        if (jj < jhi) {
            int jn = jbase + jj + 1;
            jn = min(max(jn, 0), T - 1);
            xnext = x4[(xbase + jn) * 128 + dg];
        }
        ulonglong2 xp = *reinterpret_cast<ulonglong2*>(&xv);
        const float2* ep = &e2s[jj * 32 + ttb];
        #pragma unroll
        for (int k = 0; k < 16; k++) {
            float2 evf = ep[k];
            unsigned long long ev = *reinterpret_cast<unsigned long long*>(&evf);
            fma2(acc[k][0], ev, xp.x);
            fma2(acc[k][1], ev, xp.y);
        }
        xv = xnext;
    }

    #pragma unroll
    for (int k = 0; k < 16; k++) {
        const int tt = ttb + k;
        const float2 lo = *reinterpret_cast<float2*>(&acc[k][0]);
        const float2 hi = *reinterpret_cast<float2*>(&acc[k][1]);
        out4[(xbase + t0 + tt) * 128 + dg] = make_float4(lo.x, lo.y, hi.x, hi.y);
    }
}

extern "C" void kernel_launch(void* const* d_in, const int* in_sizes, int n_in,
                              void* d_out, int out_size) {
    const float* x  = (const float*)d_in[0];
    const float* Wt = (const float*)d_in[1];
    const float* Wx = (const float*)d_in[2];
    const float* bh = (const float*)d_in[3];
    const float* Wa = (const float*)d_in[4];
    const float* ba = (const float*)d_in[5];
    float* out = (float*)d_out;

    float* gq;
    float* gk;
    cudaGetSymbolAddress((void**)&gq, g_q);
    cudaGetSymbolAddress((void**)&gk, g_k);

    qk_kernel<<<(B * T) / 8, 128>>>((const float4*)x, Wt, Wx,
                                    (const float4*)bh,
                                    (float4*)gq, (float4*)gk);
    attn_kernel<<<(B * T) / TT, 256>>>((const float4*)x, gq, gk, Wa, ba,
                                       (float4*)out);
}

// round 3
// speedup vs baseline: 2.0740x; 1.0734x over previous
#include <cuda_runtime.h>
#include <cuda_bf16.h>
#include <math.h>

#define B 4
#define T 1024
#define D 512
#define U 32
#define WIDTH 64
#define EPS 1e-7f
#define TT 16                 // t-tile per block in attn kernel
#define JW 79                 // window rows per tile: TT + WIDTH - 1

// Scratch: q (bh folded) and k projections, [B,T,U]
__device__ __align__(16) float g_q[B * T * U];
__device__ __align__(16) float g_k[B * T * U];

typedef unsigned long long ull;

__device__ __forceinline__ void fma2(ull& acc, ull a, ull b) {
    asm("fma.rn.f32x2 %0, %1, %2, %0;" : "+l"(acc) : "l"(a), "l"(b));
}
__device__ __forceinline__ ull add2(ull a, ull b) {
    ull r; asm("add.rn.f32x2 %0, %1, %2;" : "=l"(r) : "l"(a), "l"(b)); return r;
}
__device__ __forceinline__ ull dup2(float v) {
    ull r; asm("mov.b64 %0, {%1, %1};" : "=l"(r) : "f"(v)); return r;
}

// ---------------------------------------------------------------------------
// Kernel A: q = x@Wt + bh ; k = x@Wx.
// 16 rows / block, 512 threads, grid 256. Split-K by 2 (part = tid>>8).
// thread: g = tid&15 (4-u group; g<8 -> Wt, g>=8 -> Wx), r = (tid>>4)&15.
// ---------------------------------------------------------------------------
__global__ __launch_bounds__(512) void qk_kernel(
    const float4* __restrict__ x4,
    const float4* __restrict__ Wt4,
    const float4* __restrict__ Wx4,
    const float4* __restrict__ bh4,
    float4* __restrict__ gq4,
    float4* __restrict__ gk4) {
    __shared__ float xs[16 * 513];          // padded rows, ~32.8 KB
    __shared__ ull   red[256][2];           // split-K partials, 4 KB

    const int tid  = threadIdx.x;
    const int row0 = blockIdx.x * 16;

    // stage 16 x rows (scalar stores into padded layout)
    for (int i = tid; i < 16 * 128; i += 512) {
        const int r = i >> 7, c = i & 127;
        float4 v = x4[(size_t)(row0 + r) * 128 + c];
        float* dst = &xs[r * 513 + c * 4];
        dst[0] = v.x; dst[1] = v.y; dst[2] = v.z; dst[3] = v.w;
    }
    __syncthreads();

    const int g    = tid & 15;
    const int r    = (tid >> 4) & 15;
    const int part = tid >> 8;              // 0 or 1

    const ulonglong2* Wb = (g < 8)
        ? reinterpret_cast<const ulonglong2*>(Wt4) + (g & 7)
        : reinterpret_cast<const ulonglong2*>(Wx4) + (g & 7);

    ull a0 = 0ULL, a1 = 0ULL;
    const float* xr = &xs[r * 513 + part * 256];
    const ulonglong2* Wp = Wb + (size_t)part * 256 * 8;

    #pragma unroll 8
    for (int d = 0; d < 256; d++) {
        ull xp = dup2(xr[d]);
        ulonglong2 wv = Wp[d * 8];
        fma2(a0, xp, wv.x);
        fma2(a1, xp, wv.y);
    }

    if (part == 1) {
        red[tid & 255][0] = a0;
        red[tid & 255][1] = a1;
    }
    __syncthreads();

    if (part == 0) {
        a0 = add2(a0, red[tid][0]);
        a1 = add2(a1, red[tid][1]);
        const float2 f0 = *reinterpret_cast<float2*>(&a0);
        const float2 f1 = *reinterpret_cast<float2*>(&a1);
        const int row = row0 + r;
        if (g < 8) {
            float4 bb = bh4[g];
            gq4[(size_t)row * 8 + g] =
                make_float4(f0.x + bb.x, f0.y + bb.y, f1.x + bb.z, f1.y + bb.w);
        } else {
            gk4[(size_t)row * 8 + (g - 8)] =
                make_float4(f0.x, f0.y, f1.x, f1.y);
        }
    }
}

// ---------------------------------------------------------------------------
// Kernel B: banded attention. TT=16 t's per block, 512 threads, grid 256.
// ---------------------------------------------------------------------------
__global__ __launch_bounds__(512) void attn_kernel(
    const float4* __restrict__ x4,
    const float*  __restrict__ gq,
    const float*  __restrict__ gk,
    const float*  __restrict__ Wa,
    const float*  __restrict__ ba,
    float4* __restrict__ out4) {
    // overlay: phase 0/1 uses qs+ks; phase 2 reuses the space for e2s
    __shared__ __align__(16) char ubuf[(TT * 33 + JW * 33) * 4];  // 12544 B
    __shared__ float es[JW * 17];     // raw scores [jj][tt], padded
    __shared__ float was[U];
    __shared__ float inv_s[TT];
    __shared__ float ba_s;

    float*  qs  = reinterpret_cast<float*>(ubuf);        // [TT][33]
    float*  ks  = qs + TT * 33;                           // [JW][33]
    float2* e2s = reinterpret_cast<float2*>(ubuf);        // [JW][16], 10112 B

    const int tid   = threadIdx.x;
    const int blk   = blockIdx.x;
    const int b     = blk >> 6;           // 64 tiles per batch
    const int t0    = (blk & 63) * TT;
    const int jbase = t0 - WIDTH / 2;

    if (tid < U)  was[tid] = Wa[tid];
    if (tid == 0) ba_s = ba[0];

    for (int i = tid; i < TT * U; i += 512) {
        const int tt = i >> 5, u = i & 31;
        qs[tt * 33 + u] = gq[((size_t)(b * T + t0 + tt)) * U + u];
    }
    for (int i = tid; i < JW * U; i += 512) {
        const int jj = i >> 5, u = i & 31;
        const int j = jbase + jj;
        ks[jj * 33 + u] = (j >= 0 && j < T)
            ? gk[((size_t)(b * T + j)) * U + u] : 0.0f;
    }
    __syncthreads();

    // phase 1: scores. valid iff j in range and tt <= jj <= tt+63
    for (int idx = tid; idx < JW * TT; idx += 512) {
        const int jj = idx >> 4, tt = idx & 15;
        const int j = jbase + jj;
        float ev = 0.0f;
        if (j >= 0 && j < T && jj >= tt && jj <= tt + (WIDTH - 1)) {
            float s = 0.0f;
            #pragma unroll
            for (int u = 0; u < U; u++) {
                const float arg = qs[tt * 33 + u] + ks[jj * 33 + u];
                const float ex = __expf(2.0f * arg);
                const float th = __fdividef(ex - 1.0f, ex + 1.0f);
                s = fmaf(th, was[u], s);
            }
            ev = __expf(s + ba_s);
        }
        es[jj * 17 + tt] = ev;
    }
    __syncthreads();

    // row sums: warp w handles tt=w
    if (tid < TT * 32) {
        const int w = tid >> 5, lane = tid & 31;
        float s = 0.0f;
        for (int jj = lane; jj < JW; jj += 32) s += es[jj * 17 + w];
        #pragma unroll
        for (int off = 16; off > 0; off >>= 1)
            s += __shfl_down_sync(0xffffffffu, s, off);
        if (lane == 0) inv_s[w] = __fdividef(1.0f, s + EPS);
    }
    __syncthreads();

    // normalized duplicated weights (overwrites qs/ks)
    for (int idx = tid; idx < JW * TT; idx += 512) {
        const int jj = idx >> 4, tt = idx & 15;
        const float v = es[jj * 17 + tt] * inv_s[tt];
        e2s[jj * 16 + tt] = make_float2(v, v);
    }
    __syncthreads();

    // phase 2: v[tt][d] = sum_jj e[tt][jj] * x[jbase+jj][d]
    const int dg  = tid & 127;            // float4 group of d
    const int h   = tid >> 7;             // 0..3
    const int ttb = h * 4;

    ull acc[4][2];
    #pragma unroll
    for (int k = 0; k < 4; k++) { acc[k][0] = 0ULL; acc[k][1] = 0ULL; }

    const int jlo = ttb;
    const int jhi = ttb + 3 + (WIDTH - 1);   // <= 78
    const size_t xbase = (size_t)b * T;

    int jc0 = min(max(jbase + jlo, 0), T - 1);
    float4 xv = x4[(xbase + jc0) * 128 + dg];

    for (int jj = jlo; jj <= jhi; jj++) {
        float4 xnext = xv;
        if (jj < jhi) {
            int jn = min(max(jbase + jj + 1, 0), T - 1);
            xnext = x4[(xbase + jn) * 128 + dg];
        }
        ulonglong2 xp = *reinterpret_cast<ulonglong2*>(&xv);
        const ulonglong2* ep =
            reinterpret_cast<const ulonglong2*>(&e2s[jj * 16 + ttb]);
        ulonglong2 e01 = ep[0];
        ulonglong2 e23 = ep[1];
        fma2(acc[0][0], e01.x, xp.x); fma2(acc[0][1], e01.x, xp.y);
        fma2(acc[1][0], e01.y, xp.x); fma2(acc[1][1], e01.y, xp.y);
        fma2(acc[2][0], e23.x, xp.x); fma2(acc[2][1], e23.x, xp.y);
        fma2(acc[3][0], e23.y, xp.x); fma2(acc[3][1], e23.y, xp.y);
        xv = xnext;
    }

    #pragma unroll
    for (int k = 0; k < 4; k++) {
        const float2 lo = *reinterpret_cast<float2*>(&acc[k][0]);
        const float2 hi = *reinterpret_cast<float2*>(&acc[k][1]);
        out4[(xbase + t0 + ttb + k) * 128 + dg] =
            make_float4(lo.x, lo.y, hi.x, hi.y);
    }
}

extern "C" void kernel_launch(void* const* d_in, const int* in_sizes, int n_in,
                              void* d_out, int out_size) {
    const float* x  = (const float*)d_in[0];
    const float* Wt = (const float*)d_in[1];
    const float* Wx = (const float*)d_in[2];
    const float* bh = (const float*)d_in[3];
    const float* Wa = (const float*)d_in[4];
    const float* ba = (const float*)d_in[5];
    float* out = (float*)d_out;

    float* gq;
    float* gk;
    cudaGetSymbolAddress((void**)&gq, g_q);
    cudaGetSymbolAddress((void**)&gk, g_k);

    qk_kernel<<<(B * T) / 16, 512>>>((const float4*)x, (const float4*)Wt,
                                     (const float4*)Wx, (const float4*)bh,
                                     (float4*)gq, (float4*)gk);
    attn_kernel<<<(B * T) / TT, 512>>>((const float4*)x, gq, gk, Wa, ba,
                                       (float4*)out);
}

// round 4
// speedup vs baseline: 2.5404x; 1.2249x over previous
#include <cuda_runtime.h>
#include <cuda_bf16.h>
#include <math.h>

#define B 4
#define T 1024
#define D 512
#define U 32
#define WIDTH 64
#define EPS 1e-7f
#define TT 16                 // t-tile per block in attn kernel
#define JW 79                 // window rows per tile: TT + WIDTH - 1

// Scratch: q (bh folded) and k projections, [B,T,U]
__device__ __align__(16) float g_q[B * T * U];
__device__ __align__(16) float g_k[B * T * U];

typedef unsigned long long ull;

__device__ __forceinline__ void fma2(ull& acc, ull a, ull b) {
    asm("fma.rn.f32x2 %0, %1, %2, %0;" : "+l"(acc) : "l"(a), "l"(b));
}
__device__ __forceinline__ ull add2(ull a, ull b) {
    ull r; asm("add.rn.f32x2 %0, %1, %2;" : "=l"(r) : "l"(a), "l"(b)); return r;
}
__device__ __forceinline__ ull dup2(float v) {
    ull r; asm("mov.b64 %0, {%1, %1};" : "=l"(r) : "f"(v)); return r;
}

// Padé 7/7 tanh, clamped to |x|<=5. Max abs err ~1.1e-4 (beyond clamp), 1 MUFU.
__device__ __forceinline__ float tanh_fast(float x) {
    x = fminf(fmaxf(x, -5.0f), 5.0f);
    const float x2 = x * x;
    const float num = fmaf(fmaf(x2 + 378.0f, x2, 17325.0f), x2, 135135.0f);
    const float den = fmaf(fmaf(fmaf(28.0f, x2, 3150.0f), x2, 62370.0f), x2, 135135.0f);
    return __fdividef(x * num, den);
}

// ---------------------------------------------------------------------------
// Kernel A: q = x@Wt + bh ; k = x@Wx.
// 16 rows/block, 512 threads, grid 256, 4-way split-K over d.
// thread: g = tid&15 (4-u group; g<8 -> Wt, g>=8 -> Wx),
//         rg = (tid>>4)&7 (rows 2rg, 2rg+1), part = tid>>7 (128-d chunk).
// Each LDG.128 of W feeds 4 FFMA2 (2 rows x 4 u).
// ---------------------------------------------------------------------------
__global__ __launch_bounds__(512) void qk_kernel(
    const float4* __restrict__ x4,
    const ulonglong2* __restrict__ Wt2,
    const ulonglong2* __restrict__ Wx2,
    const float4* __restrict__ bh4,
    float4* __restrict__ gq4,
    float4* __restrict__ gk4) {
    __shared__ float xs[16 * 516];               // 33 KB, padded rows
    __shared__ ulonglong2 red[3 * 128][2];       // split-K partials, 12 KB

    const int tid  = threadIdx.x;
    const int row0 = blockIdx.x * 16;

    for (int i = tid; i < 16 * 128; i += 512) {
        const int r = i >> 7, c = i & 127;
        float4 v = x4[(size_t)(row0 + r) * 128 + c];
        float* dst = &xs[r * 516 + c * 4];
        dst[0] = v.x; dst[1] = v.y; dst[2] = v.z; dst[3] = v.w;
    }
    __syncthreads();

    const int g    = tid & 15;
    const int rg   = (tid >> 4) & 7;
    const int part = tid >> 7;                   // 0..3

    const ulonglong2* Wb = (g < 8) ? (Wt2 + g) : (Wx2 + (g - 8));
    Wb += (size_t)part * 128 * 8;

    const float* x0 = &xs[(2 * rg)     * 516 + part * 128];
    const float* x1 = &xs[(2 * rg + 1) * 516 + part * 128];

    ull a00 = 0, a01 = 0, a10 = 0, a11 = 0;
    #pragma unroll 8
    for (int d = 0; d < 128; d++) {
        ull xv0 = dup2(x0[d]);
        ull xv1 = dup2(x1[d]);
        ulonglong2 wv = Wb[d * 8];
        fma2(a00, xv0, wv.x); fma2(a01, xv0, wv.y);
        fma2(a10, xv1, wv.x); fma2(a11, xv1, wv.y);
    }

    if (part) {
        red[(part - 1) * 128 + (tid & 127)][0] = make_ulonglong2(a00, a01);
        red[(part - 1) * 128 + (tid & 127)][1] = make_ulonglong2(a10, a11);
    }
    __syncthreads();

    if (part == 0) {
        #pragma unroll
        for (int p = 0; p < 3; p++) {
            ulonglong2 r0 = red[p * 128 + tid][0];
            ulonglong2 r1 = red[p * 128 + tid][1];
            a00 = add2(a00, r0.x); a01 = add2(a01, r0.y);
            a10 = add2(a10, r1.x); a11 = add2(a11, r1.y);
        }
        const float2 f00 = *reinterpret_cast<float2*>(&a00);
        const float2 f01 = *reinterpret_cast<float2*>(&a01);
        const float2 f10 = *reinterpret_cast<float2*>(&a10);
        const float2 f11 = *reinterpret_cast<float2*>(&a11);
        const int row = row0 + 2 * rg;
        if (g < 8) {
            float4 bb = bh4[g];
            gq4[(size_t)row * 8 + g] =
                make_float4(f00.x + bb.x, f00.y + bb.y, f01.x + bb.z, f01.y + bb.w);
            gq4[(size_t)(row + 1) * 8 + g] =
                make_float4(f10.x + bb.x, f10.y + bb.y, f11.x + bb.z, f11.y + bb.w);
        } else {
            gk4[(size_t)row * 8 + (g - 8)] =
                make_float4(f00.x, f00.y, f01.x, f01.y);
            gk4[(size_t)(row + 1) * 8 + (g - 8)] =
                make_float4(f10.x, f10.y, f11.x, f11.y);
        }
    }
}

// ---------------------------------------------------------------------------
// Kernel B: banded attention. TT=16 t's per block, 512 threads, grid 256.
// ---------------------------------------------------------------------------
__global__ __launch_bounds__(512) void attn_kernel(
    const float4* __restrict__ x4,
    const float4* __restrict__ gq4,
    const float4* __restrict__ gk4,
    const float*  __restrict__ Wa,
    const float*  __restrict__ ba,
    float4* __restrict__ out4) {
    // qs/ks (phase 0/1) overlaid by e2s (phase 2)
    __shared__ __align__(16) char ubuf[(TT * 36 + JW * 36) * 4];  // 13680 B
    __shared__ float  es[JW * 17];   // raw scores [jj][tt]
    __shared__ float4 was4[8];
    __shared__ float  inv_s[TT];
    __shared__ float  ba_s;

    float*  qs  = reinterpret_cast<float*>(ubuf);   // [TT][36]
    float*  ks  = qs + TT * 36;                     // [JW][36]
    float2* e2s = reinterpret_cast<float2*>(ubuf);  // [JW][16] = 10112 B

    const int tid   = threadIdx.x;
    const int blk   = blockIdx.x;
    const int b     = blk >> 6;           // 64 tiles per batch
    const int t0    = (blk & 63) * TT;
    const int jbase = t0 - WIDTH / 2;

    if (tid < 8)  was4[tid] = ((const float4*)Wa)[tid];
    if (tid == 0) ba_s = ba[0];

    // load q rows (float4), always in range
    for (int i = tid; i < TT * 8; i += 512) {
        const int tt = i >> 3, w = i & 7;
        ((float4*)&qs[tt * 36])[w] = gq4[((size_t)(b * T + t0 + tt)) * 8 + w];
    }
    // load k window rows, zero-fill out of range
    for (int i = tid; i < JW * 8; i += 512) {
        const int jj = i >> 3, w = i & 7;
        const int j = jbase + jj;
        ((float4*)&ks[jj * 36])[w] = (j >= 0 && j < T)
            ? gk4[((size_t)(b * T + j)) * 8 + w]
            : make_float4(0.f, 0.f, 0.f, 0.f);
    }
    __syncthreads();

    // phase 1: scores
    for (int idx = tid; idx < JW * TT; idx += 512) {
        const int jj = idx >> 4, tt = idx & 15;
        const int j = jbase + jj;
        float ev = 0.0f;
        if (j >= 0 && j < T && jj >= tt && jj <= tt + (WIDTH - 1)) {
            const float4* qp = (const float4*)&qs[tt * 36];
            const float4* kp = (const float4*)&ks[jj * 36];
            float s = 0.0f;
            #pragma unroll
            for (int gi = 0; gi < 8; gi++) {
                float4 q4 = qp[gi], k4 = kp[gi], w4 = was4[gi];
                s = fmaf(tanh_fast(q4.x + k4.x), w4.x, s);
                s = fmaf(tanh_fast(q4.y + k4.y), w4.y, s);
                s = fmaf(tanh_fast(q4.z + k4.z), w4.z, s);
                s = fmaf(tanh_fast(q4.w + k4.w), w4.w, s);
            }
            ev = __expf(s + ba_s);
        }
        es[jj * 17 + tt] = ev;
    }
    __syncthreads();

    // row sums: warp w handles tt=w
    if (tid < TT * 32) {
        const int w = tid >> 5, lane = tid & 31;
        float s = 0.0f;
        for (int jj = lane; jj < JW; jj += 32) s += es[jj * 17 + w];
        #pragma unroll
        for (int off = 16; off > 0; off >>= 1)
            s += __shfl_down_sync(0xffffffffu, s, off);
        if (lane == 0) inv_s[w] = __fdividef(1.0f, s + EPS);
    }
    __syncthreads();

    // normalized duplicated weights (overwrites qs/ks)
    for (int idx = tid; idx < JW * TT; idx += 512) {
        const int jj = idx >> 4, tt = idx & 15;
        const float v = es[jj * 17 + tt] * inv_s[tt];
        e2s[jj * 16 + tt] = make_float2(v, v);
    }
    __syncthreads();

    // phase 2: v[tt][d] = sum_jj e[tt][jj] * x[jbase+jj][d]
    const int dg  = tid & 127;
    const int h   = tid >> 7;
    const int ttb = h * 4;

    // valid jj range hoisted: j in [0, T-1] and jj in [ttb, ttb+66]
    const int lo = max(ttb, -jbase);
    const int hi = min(ttb + 3 + (WIDTH - 1), (T - 1) - jbase);

    ull acc[4][2];
    #pragma unroll
    for (int k = 0; k < 4; k++) { acc[k][0] = 0ULL; acc[k][1] = 0ULL; }

    const size_t xbase = (size_t)b * T;
    const float4* xp = x4 + (xbase + jbase + lo) * 128 + dg;
    const float2* ep = e2s + lo * 16 + ttb;

    float4 xv = *xp;
    for (int jj = lo; jj <= hi; jj++) {
        float4 xn = xv;
        if (jj < hi) xn = xp[128];
        xp += 128;
        ulonglong2 xpk = *reinterpret_cast<ulonglong2*>(&xv);
        ulonglong2 e01 = *reinterpret_cast<const ulonglong2*>(ep);
        ulonglong2 e23 = *reinterpret_cast<const ulonglong2*>(ep + 2);
        ep += 16;
        fma2(acc[0][0], e01.x, xpk.x); fma2(acc[0][1], e01.x, xpk.y);
        fma2(acc[1][0], e01.y, xpk.x); fma2(acc[1][1], e01.y, xpk.y);
        fma2(acc[2][0], e23.x, xpk.x); fma2(acc[2][1], e23.x, xpk.y);
        fma2(acc[3][0], e23.y, xpk.x); fma2(acc[3][1], e23.y, xpk.y);
        xv = xn;
    }

    #pragma unroll
    for (int k = 0; k < 4; k++) {
        const float2 lo2 = *reinterpret_cast<float2*>(&acc[k][0]);
        const float2 hi2 = *reinterpret_cast<float2*>(&acc[k][1]);
        out4[(xbase + t0 + ttb + k) * 128 + dg] =
            make_float4(lo2.x, lo2.y, hi2.x, hi2.y);
    }
}

extern "C" void kernel_launch(void* const* d_in, const int* in_sizes, int n_in,
                              void* d_out, int out_size) {
    const float* x  = (const float*)d_in[0];
    const float* Wt = (const float*)d_in[1];
    const float* Wx = (const float*)d_in[2];
    const float* bh = (const float*)d_in[3];
    const float* Wa = (const float*)d_in[4];
    const float* ba = (const float*)d_in[5];
    float* out = (float*)d_out;

    float* gq;
    float* gk;
    cudaGetSymbolAddress((void**)&gq, g_q);
    cudaGetSymbolAddress((void**)&gk, g_k);

    qk_kernel<<<(B * T) / 16, 512>>>((const float4*)x,
                                     (const ulonglong2*)Wt,
                                     (const ulonglong2*)Wx,
                                     (const float4*)bh,
                                     (float4*)gq, (float4*)gk);
    attn_kernel<<<(B * T) / TT, 512>>>((const float4*)x,
                                       (const float4*)gq, (const float4*)gk,
                                       Wa, ba, (float4*)out);
}